// round 15
// baseline (speedup 1.0000x reference)
#include <cuda_runtime.h>
#include <cuda_bf16.h>
#include <math.h>

#define B_TOT   32768
#define OBS_DIM 256
#define HID     64
#define FEAT    128
#define N_OPT   8
#define ACT_N   18
#define TB      128
#define PB_CAP  34048          // 266*128: padded sort capacity
#define EGRID   264            // ceil((32768 + 7*127)/128)

typedef unsigned u32;

// ---------------- scratch ----------------
__device__ u32  g_stateh[PB_CAP * 64];   // state rows at PADDED sorted position
__device__ u32  g_statel[PB_CAP * 64];
__device__ int  g_perm[PB_CAP];
__device__ int  g_counts[N_OPT];
__device__ int  g_cursor[N_OPT];
__device__ int  g_base[N_OPT];
__device__ int  g_kcnt[N_OPT];
// pre-split expert weights (written by trunk, read by expert)
__device__ u32  d_oW1h[8 * 64 * 64], d_oW1l[8 * 64 * 64];
__device__ u32  d_oW2h[8 * 24 * 32], d_oW2l[8 * 24 * 32];

// ---------------- helpers ----------------
__device__ __forceinline__ void cp16(u32 dst, const void* src) {
    asm volatile("cp.async.cg.shared.global [%0], [%1], 16;" :: "r"(dst), "l"(src));
}
__device__ __forceinline__ void cp_commit() {
    asm volatile("cp.async.commit_group;");
}
__device__ __forceinline__ void cp_wait_all() {
    asm volatile("cp.async.wait_group 0;" ::: "memory");
}
// truncation split (no F2FP)
__device__ __forceinline__ void splitT(float x, float y, u32& hi, u32& lo) {
    u32 xb = __float_as_uint(x), yb = __float_as_uint(y);
    hi = __byte_perm(xb, yb, 0x7632);
    float lx = x - __uint_as_float(xb & 0xFFFF0000u);
    float ly = y - __uint_as_float(yb & 0xFFFF0000u);
    lo = __byte_perm(__float_as_uint(lx), __float_as_uint(ly), 0x7632);
}
__device__ __forceinline__ void mma16816(float d[4], const u32 a[4], const u32 b[2]) {
    asm("mma.sync.aligned.m16n8k16.row.col.f32.bf16.bf16.f32 "
        "{%0,%1,%2,%3},{%4,%5,%6,%7},{%8,%9},{%0,%1,%2,%3};"
        : "+f"(d[0]), "+f"(d[1]), "+f"(d[2]), "+f"(d[3])
        : "r"(a[0]), "r"(a[1]), "r"(a[2]), "r"(a[3]), "r"(b[0]), "r"(b[1]));
}
__device__ __forceinline__ void ldsm4(u32 r[4], u32 addr) {
    asm volatile("ldmatrix.sync.aligned.m8n8.x4.shared.b16 {%0,%1,%2,%3}, [%4];"
        : "=r"(r[0]), "=r"(r[1]), "=r"(r[2]), "=r"(r[3]) : "r"(addr));
}
__device__ __forceinline__ void ldsm2(u32 r[2], u32 addr) {
    asm volatile("ldmatrix.sync.aligned.m8n8.x2.shared.b16 {%0,%1}, [%2];"
        : "=r"(r[0]), "=r"(r[1]) : "r"(addr));
}

template <int KSTEPS>
__device__ __forceinline__ void warp_mma64(
    const u32* Ahi, const u32* Alo, int sa,
    const u32* Whi, const u32* Wlo, int sw,
    int m0, int lane, float acc[8][4])
{
    const int mat = lane >> 3, rin = lane & 7;
    u32 aOff = (u32)(((m0 + rin + ((mat & 1) << 3)) * sa + ((mat >> 1) << 2)) << 2);
    u32 aHiA = (u32)__cvta_generic_to_shared(Ahi) + aOff;
    u32 aLoA = (u32)__cvta_generic_to_shared(Alo) + aOff;
    u32 bRel = (u32)((((((mat >> 1) << 3)) + rin) * sw + ((mat & 1) << 2)) << 2);
    u32 wHiB = (u32)__cvta_generic_to_shared(Whi) + bRel;
    u32 wLoB = (u32)__cvta_generic_to_shared(Wlo) + bRel;

#pragma unroll
    for (int ks = 0; ks < KSTEPS; ks++) {
        const u32 kb = ks * 32;
        u32 ah[4], al[4];
        ldsm4(ah, aHiA + kb);
        ldsm4(al, aLoA + kb);
#pragma unroll
        for (int nb = 0; nb < 4; nb++) {
            u32 bh[4], bl[4];
            u32 off = kb + (u32)(nb * 16 * sw * 4);
            ldsm4(bh, wHiB + off);
            ldsm4(bl, wLoB + off);
            mma16816(acc[2 * nb],     ah, bh + 0);
            mma16816(acc[2 * nb + 1], ah, bh + 2);
            mma16816(acc[2 * nb],     al, bh + 0);
            mma16816(acc[2 * nb + 1], al, bh + 2);
            mma16816(acc[2 * nb],     ah, bl + 0);
            mma16816(acc[2 * nb + 1], ah, bl + 2);
        }
    }
}

// =====================================================================
// Kernel 0: histogram only (ballot-aggregated)
// =====================================================================
__global__ void hist_kernel(const int* __restrict__ opt)
{
    __shared__ int s_cnt[N_OPT];
    int tid = threadIdx.x;
    if (tid < N_OPT) s_cnt[tid] = 0;
    __syncthreads();
    int o = opt[blockIdx.x * 256 + tid];
#pragma unroll
    for (int q = 0; q < N_OPT; q++) {
        unsigned b = __ballot_sync(0xffffffffu, o == q);
        if ((tid & 31) == 0 && b) atomicAdd(&s_cnt[q], __popc(b));
    }
    __syncthreads();
    if (tid < N_OPT && s_cnt[tid]) atomicAdd(&g_counts[tid], s_cnt[tid]);
}

// =====================================================================
// Kernel 1: trunk (inline fW split) + distributed oW split + padded scatter
// smem u32 layout (27136 = 108,544 B):
//  aHi 0 | aLo 4608 | hHi 9216 | hLo 13824 | wH 18432 | wL 20736 | F32 23040..27136
//  s_pt (2048 f32) aliases aHi in phase 2
// =====================================================================
__global__ void __launch_bounds__(256, 2) trunk_kernel(
    const float* __restrict__ obs, const int* __restrict__ opt,
    const float* __restrict__ fW1, const float* __restrict__ fb1,
    const float* __restrict__ fW2, const float* __restrict__ fb2,
    const float* __restrict__ pW,  const float* __restrict__ pb,
    const float* __restrict__ tW,  const float* __restrict__ tb,
    const float* __restrict__ oW1, const float* __restrict__ oW2,
    float* __restrict__ out_opt, float* __restrict__ out_term)
{
    extern __shared__ u32 smu[];
    u32* aHi = smu;
    u32* aLo = smu + 4608;
    u32* hHi = smu + 9216;
    u32* hLo = smu + 13824;
    u32* wH  = smu + 18432;
    u32* wL  = smu + 20736;
    u32* F32 = smu + 23040;          // 4096 u32 raw f32 stage
    float* fF32 = (float*)F32;
    float* s_pt = (float*)smu;       // alias aHi/aLo in phase 2
    __shared__ int s_opt[TB];
    __shared__ int s_pos[TB];
    __shared__ int s_cnt[N_OPT];
    __shared__ int s_base[N_OPT];

    const int tid  = threadIdx.x;
    const int r0   = blockIdx.x * TB;
    const int w    = tid >> 5, lane = tid & 31;
    const int g    = lane >> 2, t = lane & 3;
    const int m0   = w * 16;

    // ---------- prologue cp.async: f32 fW1 chunk0 ----------
#pragma unroll
    for (int it = 0; it < 4; it++) {
        int q = tid + it * 256;                 // 1024 uint4 = 4096 u32
        int row = q >> 4, p4 = (q & 15) << 2;
        cp16((u32)__cvta_generic_to_shared(F32 + row * 64 + p4),
             fW1 + row * OBS_DIM + p4);
    }
    cp_commit();

    // ---------- distributed oW1/oW2 pre-split (fire-and-forget) ----------
    {
        int i = blockIdx.x * 256 + tid;         // 0..65535 >= 38912 items
        if (i < 32768) {                        // oW1: 32768 float2 pairs
            float2 v = ((const float2*)oW1)[i];
            u32 hi, lo;
            splitT(v.x, v.y, hi, lo);
            d_oW1h[i] = hi;
            d_oW1l[i] = lo;
        } else if (i < 32768 + 6144) {          // oW2 image [8][24][32]
            int k = i - 32768;
            int o = k / 768, row = (k % 768) / 32, p = k % 32;
            u32 hi = 0, lo = 0;
            if (row < ACT_N) {
                float2 v = *(const float2*)(oW2 + (o * ACT_N + row) * HID + 2 * p);
                splitT(v.x, v.y, hi, lo);
            }
            d_oW2h[k] = hi;
            d_oW2l[k] = lo;
        }
    }

    // ---------- sort positions (padded bases from g_counts) ----------
    if (tid < N_OPT) s_cnt[tid] = 0;
    if (tid < TB) s_opt[tid] = opt[r0 + tid];
    __syncthreads();
    int loc = 0;
    if (tid < TB) loc = atomicAdd(&s_cnt[s_opt[tid]], 1);
    __syncthreads();
    if (tid < N_OPT) {
        int base = 0;
#pragma unroll
        for (int q = 0; q < N_OPT; q++)
            base += (q < tid) ? ((g_counts[q] + 127) & ~127) : 0;
        s_base[tid] = base + atomicAdd(&g_cursor[tid], s_cnt[tid]);
        g_base[tid] = base;
        g_kcnt[tid] = g_counts[tid];
    }
    __syncthreads();
    if (tid < TB) {
        int p = s_base[s_opt[tid]] + loc;
        s_pos[tid] = p;
        g_perm[p] = r0 + tid;
    }

    // ---------- obs chunk0 split ----------
#pragma unroll
    for (int it = 0; it < 16; it++) {
        int e = tid + it * 256;
        int row = e >> 5, p = e & 31;
        float2 o2 = *(const float2*)(obs + (r0 + row) * OBS_DIM + 2 * p);
        splitT(o2.x, o2.y, aHi[row * 36 + p], aLo[row * 36 + p]);
    }

    // ---------- phase 1: h = relu(obs @ fW1^T + fb1), 4 chunks ----------
    float accA[8][4];
#pragma unroll
    for (int i = 0; i < 8; i++)
#pragma unroll
        for (int j = 0; j < 4; j++) accA[i][j] = 0.f;

    float2 ov[16];
#pragma unroll
    for (int kc = 0; kc < 4; kc++) {
        u32* cAhi = (kc & 1) ? hHi : aHi;
        u32* cAlo = (kc & 1) ? hLo : aLo;
        cp_wait_all();
        __syncthreads();                 // F32[kc] + obs[kc] ready; prior MMA reads done
        // split f32 weights -> wH/wL
#pragma unroll
        for (int it = 0; it < 8; it++) {
            int e = tid + it * 256;      // 2048 float2
            int row = e >> 5, p = e & 31;
            float2 v = *(const float2*)(fF32 + row * 64 + 2 * p);
            splitT(v.x, v.y, wH[row * 36 + p], wL[row * 36 + p]);
        }
        __syncthreads();                 // wH/wL visible; F32 reads done
        if (kc < 3) {
            // next f32 weight chunk
#pragma unroll
            for (int it = 0; it < 4; it++) {
                int q = tid + it * 256;
                int row = q >> 4, p4 = (q & 15) << 2;
                cp16((u32)__cvta_generic_to_shared(F32 + row * 64 + p4),
                     fW1 + row * OBS_DIM + (kc + 1) * 64 + p4);
            }
            cp_commit();
            // obs prefetch to regs
#pragma unroll
            for (int it = 0; it < 16; it++) {
                int e = tid + it * 256;
                int row = e >> 5, p = e & 31;
                ov[it] = *(const float2*)(obs + (r0 + row) * OBS_DIM + (kc + 1) * 64 + 2 * p);
            }
        }
        warp_mma64<4>(cAhi, cAlo, 36, wH, wL, 36, m0, lane, accA);
        if (kc < 3) {
            u32* nAhi = (kc & 1) ? aHi : hHi;
            u32* nAlo = (kc & 1) ? aLo : hLo;
#pragma unroll
            for (int it = 0; it < 16; it++) {
                int e = tid + it * 256;
                int row = e >> 5, p = e & 31;
                splitT(ov[it].x, ov[it].y, nAhi[row * 36 + p], nAlo[row * 36 + p]);
            }
        }
    }
    __syncthreads();   // chunk-3 MMA reads of hHi/hLo done before h writes

    const int r1 = m0 + g, r2 = m0 + g + 8;

    // epilogue -> h bf16 hi/lo (into hHi/hLo)
#pragma unroll
    for (int nt = 0; nt < 8; nt++) {
        int c = nt * 8 + 2 * t;
        float b0 = fb1[c], b1 = fb1[c + 1];
        float v0 = fmaxf(accA[nt][0] + b0, 0.f), v1 = fmaxf(accA[nt][1] + b1, 0.f);
        splitT(v0, v1, hHi[r1 * 36 + (c >> 1)], hLo[r1 * 36 + (c >> 1)]);
        float v2 = fmaxf(accA[nt][2] + b0, 0.f), v3 = fmaxf(accA[nt][3] + b1, 0.f);
        splitT(v2, v3, hHi[r2 * 36 + (c >> 1)], hLo[r2 * 36 + (c >> 1)]);
    }

    // ---------- phase 2: state = relu(h @ fW2^T + fb2), two 64-col halves ----------
    // stage f32 fW2 half0 + pW/tW (s_pt aliases aHi — free after phase 1)
#pragma unroll
    for (int it = 0; it < 4; it++) {
        int q = tid + it * 256;
        int row = q >> 4, p4 = (q & 15) << 2;
        cp16((u32)__cvta_generic_to_shared(F32 + row * 64 + p4),
             fW2 + row * HID + p4);
    }
#pragma unroll
    for (int it = 0; it < 2; it++) {
        int q = tid + it * 256;                 // 512 uint4 = 2048 f32
        const float* src = (q < 256) ? (pW + q * 4) : (tW + (q - 256) * 4);
        cp16((u32)__cvta_generic_to_shared(s_pt + q * 4), src);
    }
    cp_commit();

    const int o1 = s_opt[r1], o2v = s_opt[r2];
    const int p1 = s_pos[r1], p2 = s_pos[r2];
    float pv1 = 0.f, tv1 = 0.f, pv2 = 0.f, tv2 = 0.f;

#pragma unroll
    for (int nh = 0; nh < 2; nh++) {
        cp_wait_all();
        __syncthreads();                 // F32[nh] ready; prior MMA reads of wH/wL done
#pragma unroll
        for (int it = 0; it < 8; it++) {
            int e = tid + it * 256;
            int row = e >> 5, p = e & 31;
            float2 v = *(const float2*)(fF32 + row * 64 + 2 * p);
            splitT(v.x, v.y, wH[row * 36 + p], wL[row * 36 + p]);
        }
        __syncthreads();                 // wH/wL visible; F32 reads done
        if (nh == 0) {
#pragma unroll
            for (int it = 0; it < 4; it++) {
                int q = tid + it * 256;
                int row = q >> 4, p4 = (q & 15) << 2;
                cp16((u32)__cvta_generic_to_shared(F32 + row * 64 + p4),
                     fW2 + (64 + row) * HID + p4);
            }
            cp_commit();
        }

        float acc2[8][4];
#pragma unroll
        for (int i = 0; i < 8; i++)
#pragma unroll
            for (int j = 0; j < 4; j++) acc2[i][j] = 0.f;
        warp_mma64<4>(hHi, hLo, 36, wH, wL, 36, m0, lane, acc2);

#pragma unroll
        for (int nt = 0; nt < 8; nt++) {
            int c = nh * 64 + nt * 8 + 2 * t;
            float b0 = fb2[c], b1 = fb2[c + 1];
            float v0 = fmaxf(acc2[nt][0] + b0, 0.f);
            float v1 = fmaxf(acc2[nt][1] + b1, 0.f);
            float v2 = fmaxf(acc2[nt][2] + b0, 0.f);
            float v3 = fmaxf(acc2[nt][3] + b1, 0.f);
            u32 hi, lo;
            splitT(v0, v1, hi, lo);
            g_stateh[p1 * 64 + (c >> 1)] = hi;
            g_statel[p1 * 64 + (c >> 1)] = lo;
            splitT(v2, v3, hi, lo);
            g_stateh[p2 * 64 + (c >> 1)] = hi;
            g_statel[p2 * 64 + (c >> 1)] = lo;
            pv1 += v0 * s_pt[o1 * 128 + c] + v1 * s_pt[o1 * 128 + c + 1];
            tv1 += v0 * s_pt[1024 + o1 * 128 + c] + v1 * s_pt[1024 + o1 * 128 + c + 1];
            pv2 += v2 * s_pt[o2v * 128 + c] + v3 * s_pt[o2v * 128 + c + 1];
            tv2 += v2 * s_pt[1024 + o2v * 128 + c] + v3 * s_pt[1024 + o2v * 128 + c + 1];
        }
    }

#pragma unroll
    for (int o = 1; o <= 2; o <<= 1) {
        pv1 += __shfl_xor_sync(0xffffffffu, pv1, o);
        tv1 += __shfl_xor_sync(0xffffffffu, tv1, o);
        pv2 += __shfl_xor_sync(0xffffffffu, pv2, o);
        tv2 += __shfl_xor_sync(0xffffffffu, tv2, o);
    }
    if (t == 0) {
        out_opt[r0 + r1]  = pv1 + pb[o1];
        out_term[r0 + r1] = 1.f / (1.f + expf(-(tv1 + tb[o1])));
        out_opt[r0 + r2]  = pv2 + pb[o2v];
        out_term[r0 + r2] = 1.f / (1.f + expf(-(tv2 + tb[o2v])));
    }
}

// =====================================================================
// Kernel 2: expert — ONE option per block (padded sort)
// =====================================================================
__global__ void __launch_bounds__(256, 2) expert_kernel(
    const float* __restrict__ ob1, const float* __restrict__ ob2,
    const int* __restrict__ act, float* __restrict__ out_logp)
{
    extern __shared__ u32 smu[];
    u32* stHi = smu;
    u32* stLo = smu + 8704;
    u32* wHi  = smu + 17408;
    u32* wLo  = smu + 21760;
    u32* w2h  = smu + 26112;
    u32* w2l  = smu + 26976;
    __shared__ int s_idx[TB];
    __shared__ int s_act[TB];
    __shared__ int s_gb[N_OPT];
    __shared__ int s_gc[N_OPT];

    const int tid  = threadIdx.x;
    const int r0   = blockIdx.x * TB;
    const int w    = tid >> 5, lane = tid & 31;
    const int g    = lane >> 2, t = lane & 3;
    const int m0   = w * 16;

    // state rows: sequential stream from padded positions
#pragma unroll
    for (int it = 0; it < 8; it++) {
        int q = tid + it * 256;
        int row = q >> 4, p4 = (q & 15) << 2;
        cp16((u32)__cvta_generic_to_shared(stHi + row * 68 + p4), g_stateh + (r0 + row) * 64 + p4);
        cp16((u32)__cvta_generic_to_shared(stLo + row * 68 + p4), g_statel + (r0 + row) * 64 + p4);
    }
    cp_commit();

    if (tid < N_OPT) { s_gb[tid] = g_base[tid]; s_gc[tid] = g_kcnt[tid]; }
    if (blockIdx.x == 0 && tid < N_OPT) { g_counts[tid] = 0; g_cursor[tid] = 0; }
    __syncthreads();

    int o = 0;
#pragma unroll
    for (int q = 1; q < N_OPT; q++) o += (r0 >= s_gb[q]) ? 1 : 0;
    const int gb = s_gb[o], gc = s_gc[o];

    if (tid < TB) {
        int gi = g_perm[r0 + tid];
        s_idx[tid] = gi;
        s_act[tid] = act[gi & (B_TOT - 1)];
    }

#pragma unroll
    for (int it = 0; it < 4; it++) {
        int q = tid + it * 256;
        int row = q >> 4, p4 = (q & 15) << 2;
        cp16((u32)__cvta_generic_to_shared(wHi + row * 68 + p4), d_oW1h + (o * 64 + row) * 64 + p4);
        cp16((u32)__cvta_generic_to_shared(wLo + row * 68 + p4), d_oW1l + (o * 64 + row) * 64 + p4);
    }
    if (tid < 192) {
        int row = tid >> 3, p4 = (tid & 7) << 2;
        cp16((u32)__cvta_generic_to_shared(w2h + row * 36 + p4), d_oW2h + o * 768 + row * 32 + p4);
        cp16((u32)__cvta_generic_to_shared(w2l + row * 36 + p4), d_oW2l + o * 768 + row * 32 + p4);
    }
    cp_commit();
    cp_wait_all();
    __syncthreads();

    // MMA1
    float acc[8][4];
#pragma unroll
    for (int i = 0; i < 8; i++)
#pragma unroll
        for (int q = 0; q < 4; q++) acc[i][q] = 0.f;
    warp_mma64<8>(stHi, stLo, 68, wHi, wLo, 68, m0, lane, acc);

    // register epilogue -> A-fragments
    u32 ah1[8], al1[8], ah2[8], al2[8];
#pragma unroll
    for (int nt = 0; nt < 8; nt++) {
        int c = nt * 8 + 2 * t;
        float b0 = ob1[o * HID + c], b1 = ob1[o * HID + c + 1];
        splitT(fmaxf(acc[nt][0] + b0, 0.f), fmaxf(acc[nt][1] + b1, 0.f), ah1[nt], al1[nt]);
        splitT(fmaxf(acc[nt][2] + b0, 0.f), fmaxf(acc[nt][3] + b1, 0.f), ah2[nt], al2[nt]);
    }

    // MMA2: logits
    float accL[3][4];
#pragma unroll
    for (int i = 0; i < 3; i++)
#pragma unroll
        for (int q = 0; q < 4; q++) accL[i][q] = 0.f;
    {
        const int mat = lane >> 3, rin = lane & 7;
        u32 b4h = (u32)__cvta_generic_to_shared(w2h) +
                  (u32)(((((mat >> 1) << 3) + rin) * 36 + ((mat & 1) << 2)) << 2);
        u32 b4l = (u32)__cvta_generic_to_shared(w2l) +
                  (u32)(((((mat >> 1) << 3) + rin) * 36 + ((mat & 1) << 2)) << 2);
        const int l16 = lane & 15;
        u32 b2off = (u32)(((16 + (l16 & 7)) * 36 + (((l16 >> 3) & 1) << 2)) << 2);
        u32 b2h = (u32)__cvta_generic_to_shared(w2h) + b2off;
        u32 b2l = (u32)__cvta_generic_to_shared(w2l) + b2off;
#pragma unroll
        for (int ks = 0; ks < 4; ks++) {
            u32 kb = ks * 32;
            u32 ah[4] = { ah1[2 * ks], ah2[2 * ks], ah1[2 * ks + 1], ah2[2 * ks + 1] };
            u32 al[4] = { al1[2 * ks], al2[2 * ks], al1[2 * ks + 1], al2[2 * ks + 1] };
            u32 bh[4], bl[4], bh2[2], bl2[2];
            ldsm4(bh, b4h + kb);
            ldsm4(bl, b4l + kb);
            ldsm2(bh2, b2h + kb);
            ldsm2(bl2, b2l + kb);
            mma16816(accL[0], ah, bh + 0);
            mma16816(accL[1], ah, bh + 2);
            mma16816(accL[2], ah, bh2);
            mma16816(accL[0], al, bh + 0);
            mma16816(accL[1], al, bh + 2);
            mma16816(accL[2], al, bh2);
            mma16816(accL[0], ah, bl + 0);
            mma16816(accL[1], ah, bl + 2);
            mma16816(accL[2], ah, bl2);
        }
    }

    // softmax on fragments; skip hole rows
#pragma unroll
    for (int half = 0; half < 2; half++) {
        int rr = m0 + g + half * 8;
        float v[3][2];
#pragma unroll
        for (int nt = 0; nt < 3; nt++)
#pragma unroll
            for (int i = 0; i < 2; i++) {
                int c = nt * 8 + 2 * t + i;
                v[nt][i] = (c < ACT_N) ? accL[nt][half * 2 + i] + ob2[o * ACT_N + c]
                                       : -INFINITY;
            }
        float m = v[0][0];
#pragma unroll
        for (int nt = 0; nt < 3; nt++)
#pragma unroll
            for (int i = 0; i < 2; i++) m = fmaxf(m, v[nt][i]);
        m = fmaxf(m, __shfl_xor_sync(0xffffffffu, m, 1));
        m = fmaxf(m, __shfl_xor_sync(0xffffffffu, m, 2));
        float S = 0.f;
#pragma unroll
        for (int nt = 0; nt < 3; nt++)
#pragma unroll
            for (int i = 0; i < 2; i++) S += expf(v[nt][i] - m);
        S += __shfl_xor_sync(0xffffffffu, S, 1);
        S += __shfl_xor_sync(0xffffffffu, S, 2);
        int a = s_act[rr];
        float cand = 0.f;
#pragma unroll
        for (int nt = 0; nt < 3; nt++)
#pragma unroll
            for (int i = 0; i < 2; i++) {
                int c = nt * 8 + 2 * t + i;
                cand = (c == a) ? v[nt][i] : cand;
            }
        cand += __shfl_xor_sync(0xffffffffu, cand, 1);
        cand += __shfl_xor_sync(0xffffffffu, cand, 2);
        bool real = (r0 + rr - gb) < gc;
        if (t == 0 && real)
            out_logp[s_idx[rr]] = cand - m - logf(S);
    }
}

// =====================================================================
extern "C" void kernel_launch(void* const* d_in, const int* in_sizes, int n_in,
                              void* d_out, int out_size)
{
    const float* obs = (const float*)d_in[0];
    const int*   act = (const int*)  d_in[1];
    const int*   opt = (const int*)  d_in[2];
    const float* fW1 = (const float*)d_in[3];
    const float* fb1 = (const float*)d_in[4];
    const float* fW2 = (const float*)d_in[5];
    const float* fb2 = (const float*)d_in[6];
    const float* pW  = (const float*)d_in[7];
    const float* pb  = (const float*)d_in[8];
    const float* tW  = (const float*)d_in[9];
    const float* tb  = (const float*)d_in[10];
    const float* oW1 = (const float*)d_in[11];
    const float* ob1 = (const float*)d_in[12];
    const float* oW2 = (const float*)d_in[13];
    const float* ob2 = (const float*)d_in[14];

    float* out_logp = (float*)d_out;
    float* out_opt  = out_logp + B_TOT;
    float* out_term = out_logp + 2 * B_TOT;

    const int smem1 = 27136 * 4;   // 108,544 B
    const int smem4 = 27840 * 4;   // 111,360 B
    cudaFuncSetAttribute(trunk_kernel,  cudaFuncAttributeMaxDynamicSharedMemorySize, smem1);
    cudaFuncSetAttribute(expert_kernel, cudaFuncAttributeMaxDynamicSharedMemorySize, smem4);

    hist_kernel<<<B_TOT / 256, 256>>>(opt);
    trunk_kernel<<<B_TOT / TB, 256, smem1>>>(obs, opt, fW1, fb1, fW2, fb2,
                                             pW, pb, tW, tb, oW1, oW2,
                                             out_opt, out_term);
    expert_kernel<<<EGRID, 256, smem4>>>(ob1, ob2, act, out_logp);
}

// round 16
// speedup vs baseline: 1.1704x; 1.1704x over previous
#include <cuda_runtime.h>
#include <cuda_bf16.h>
#include <math.h>

#define B_TOT   32768
#define OBS_DIM 256
#define HID     64
#define FEAT    128
#define N_OPT   8
#define ACT_N   18
#define TB      128
#define NTILE   266            // padded tile capacity
#define EGRID   264            // ceil((32768 + 7*127)/128)

typedef unsigned u32;

// ---------------- scratch ----------------
// state stored as per-block TILE IMAGES: [tile][128*68] u32 (holes unwritten=0)
__device__ u32  g_sth[NTILE * 8704];
__device__ u32  g_stl[NTILE * 8704];
__device__ int  g_perm[NTILE * TB];
__device__ int  g_counts[N_OPT];
__device__ int  g_cursor[N_OPT];
__device__ int  g_base[N_OPT];
__device__ int  g_kcnt[N_OPT];
// pre-split weights; oW1/oW2 in padded IMAGE layouts for bulk copy
__device__ u32  d_fW1h[64 * 128],   d_fW1l[64 * 128];
__device__ u32  d_fW2h[128 * 32],   d_fW2l[128 * 32];
__device__ u32  d_oW1h[8 * 4352],   d_oW1l[8 * 4352];   // [o][64*68]
__device__ u32  d_oW2h[8 * 864],    d_oW2l[8 * 864];    // [o][24*36]

// ---------------- helpers ----------------
__device__ __forceinline__ void cp16(u32 dst, const void* src) {
    asm volatile("cp.async.cg.shared.global [%0], [%1], 16;" :: "r"(dst), "l"(src));
}
__device__ __forceinline__ void cp_commit() {
    asm volatile("cp.async.commit_group;");
}
__device__ __forceinline__ void cp_wait_all() {
    asm volatile("cp.async.wait_group 0;" ::: "memory");
}
__device__ __forceinline__ void bulkcp(u32 dst, const void* src, u32 bytes, u32 mbar) {
    asm volatile(
        "cp.async.bulk.shared::cta.global.mbarrier::complete_tx::bytes [%0], [%1], %2, [%3];"
        :: "r"(dst), "l"(src), "r"(bytes), "r"(mbar) : "memory");
}
__device__ __forceinline__ void mbar_init(u32 mbar, u32 cnt) {
    asm volatile("mbarrier.init.shared.b64 [%0], %1;" :: "r"(mbar), "r"(cnt) : "memory");
}
__device__ __forceinline__ void mbar_expect(u32 mbar, u32 bytes) {
    asm volatile("mbarrier.arrive.expect_tx.shared.b64 _, [%0], %1;" :: "r"(mbar), "r"(bytes) : "memory");
}
__device__ __forceinline__ void mbar_wait(u32 mbar, u32 parity) {
    asm volatile(
        "{\n\t.reg .pred P1;\n\t"
        "W_%=:\n\t"
        "mbarrier.try_wait.parity.shared.b64 P1, [%0], %1;\n\t"
        "@P1 bra D_%=;\n\t"
        "bra W_%=;\n\t"
        "D_%=:\n\t}"
        :: "r"(mbar), "r"(parity) : "memory");
}
// round-to-nearest split (cold path)
__device__ __forceinline__ void split2(float x, float y, u32& hi, u32& lo) {
    __nv_bfloat162 h = __floats2bfloat162_rn(x, y);
    float hx = __bfloat162float(h.x);
    float hy = __bfloat162float(h.y);
    __nv_bfloat162 l = __floats2bfloat162_rn(x - hx, y - hy);
    hi = *reinterpret_cast<u32*>(&h);
    lo = *reinterpret_cast<u32*>(&l);
}
// truncation split (hot path)
__device__ __forceinline__ void splitT(float x, float y, u32& hi, u32& lo) {
    u32 xb = __float_as_uint(x), yb = __float_as_uint(y);
    hi = __byte_perm(xb, yb, 0x7632);
    float lx = x - __uint_as_float(xb & 0xFFFF0000u);
    float ly = y - __uint_as_float(yb & 0xFFFF0000u);
    lo = __byte_perm(__float_as_uint(lx), __float_as_uint(ly), 0x7632);
}
__device__ __forceinline__ void mma16816(float d[4], const u32 a[4], const u32 b[2]) {
    asm("mma.sync.aligned.m16n8k16.row.col.f32.bf16.bf16.f32 "
        "{%0,%1,%2,%3},{%4,%5,%6,%7},{%8,%9},{%0,%1,%2,%3};"
        : "+f"(d[0]), "+f"(d[1]), "+f"(d[2]), "+f"(d[3])
        : "r"(a[0]), "r"(a[1]), "r"(a[2]), "r"(a[3]), "r"(b[0]), "r"(b[1]));
}
__device__ __forceinline__ void ldsm4(u32 r[4], u32 addr) {
    asm volatile("ldmatrix.sync.aligned.m8n8.x4.shared.b16 {%0,%1,%2,%3}, [%4];"
        : "=r"(r[0]), "=r"(r[1]), "=r"(r[2]), "=r"(r[3]) : "r"(addr));
}
__device__ __forceinline__ void ldsm2(u32 r[2], u32 addr) {
    asm volatile("ldmatrix.sync.aligned.m8n8.x2.shared.b16 {%0,%1}, [%2];"
        : "=r"(r[0]), "=r"(r[1]) : "r"(addr));
}

template <int KSTEPS>
__device__ __forceinline__ void warp_mma64(
    const u32* Ahi, const u32* Alo, int sa,
    const u32* Whi, const u32* Wlo, int sw,
    int m0, int lane, float acc[8][4])
{
    const int mat = lane >> 3, rin = lane & 7;
    u32 aOff = (u32)(((m0 + rin + ((mat & 1) << 3)) * sa + ((mat >> 1) << 2)) << 2);
    u32 aHiA = (u32)__cvta_generic_to_shared(Ahi) + aOff;
    u32 aLoA = (u32)__cvta_generic_to_shared(Alo) + aOff;
    u32 bRel = (u32)((((((mat >> 1) << 3)) + rin) * sw + ((mat & 1) << 2)) << 2);
    u32 wHiB = (u32)__cvta_generic_to_shared(Whi) + bRel;
    u32 wLoB = (u32)__cvta_generic_to_shared(Wlo) + bRel;

#pragma unroll
    for (int ks = 0; ks < KSTEPS; ks++) {
        const u32 kb = ks * 32;
        u32 ah[4], al[4];
        ldsm4(ah, aHiA + kb);
        ldsm4(al, aLoA + kb);
#pragma unroll
        for (int nb = 0; nb < 4; nb++) {
            u32 bh[4], bl[4];
            u32 off = kb + (u32)(nb * 16 * sw * 4);
            ldsm4(bh, wHiB + off);
            ldsm4(bl, wLoB + off);
            mma16816(acc[2 * nb],     ah, bh + 0);
            mma16816(acc[2 * nb + 1], ah, bh + 2);
            mma16816(acc[2 * nb],     al, bh + 0);
            mma16816(acc[2 * nb + 1], al, bh + 2);
            mma16816(acc[2 * nb],     ah, bl + 0);
            mma16816(acc[2 * nb + 1], ah, bl + 2);
        }
    }
}

// =====================================================================
// Kernel 0: pre-split weights (image layouts) + opt histogram
// =====================================================================
__global__ void split_kernel(const float* __restrict__ fW1,
                             const float* __restrict__ fW2,
                             const float* __restrict__ oW1,
                             const float* __restrict__ oW2,
                             const int* __restrict__ opt)
{
    __shared__ int s_cnt[N_OPT];
    int tid = threadIdx.x;
    if (tid < N_OPT) s_cnt[tid] = 0;
    __syncthreads();
    int i = blockIdx.x * blockDim.x + tid;
    if (i < 8192) {
        float2 v = ((const float2*)fW1)[i];
        split2(v.x, v.y, d_fW1h[i], d_fW1l[i]);
    } else if (i < 12288) {
        int k = i - 8192;
        float2 v = ((const float2*)fW2)[k];
        split2(v.x, v.y, d_fW2h[k], d_fW2l[k]);
    } else if (i < 45056) {
        int k = i - 12288;                       // [o][64][64] float2
        int o = k >> 12, row = (k >> 6) & 63, c = k & 63;
        float2 v = ((const float2*)oW1)[k];
        u32 hi, lo;
        split2(v.x, v.y, hi, lo);
        d_oW1h[o * 4352 + row * 68 + c] = hi;
        d_oW1l[o * 4352 + row * 68 + c] = lo;
    } else if (i < 45056 + 8 * 24 * 32) {
        int k = i - 45056;                       // [o][24][32]
        int o = k / 768, row = (k % 768) / 32, p = k % 32;
        u32 hi = 0, lo = 0;
        if (row < ACT_N) {
            float2 v = *(const float2*)(oW2 + (o * ACT_N + row) * HID + 2 * p);
            split2(v.x, v.y, hi, lo);
        }
        d_oW2h[o * 864 + row * 36 + p] = hi;
        d_oW2l[o * 864 + row * 36 + p] = lo;
    }
    if (i < B_TOT) atomicAdd(&s_cnt[opt[i]], 1);
    __syncthreads();
    if (tid < N_OPT && s_cnt[tid]) atomicAdd(&g_counts[tid], s_cnt[tid]);
}

// =====================================================================
// Kernel 1: trunk GEMMs (pipelined), heads, state -> padded tile images
// =====================================================================
__global__ void __launch_bounds__(256, 2) trunk_kernel(
    const float* __restrict__ obs, const int* __restrict__ opt,
    const float* __restrict__ fb1, const float* __restrict__ fb2,
    const float* __restrict__ pW,  const float* __restrict__ pb,
    const float* __restrict__ tW,  const float* __restrict__ tb,
    float* __restrict__ out_opt, float* __restrict__ out_term)
{
    extern __shared__ u32 smu[];
    u32* aHi = smu;
    u32* aLo = smu + 4608;
    u32* w0H = smu + 9216;
    u32* w0L = smu + 11520;
    u32* w1H = smu + 13824;
    u32* w1L = smu + 16128;
    u32* hHi = smu + 18432;
    u32* hLo = smu + 23040;
    float* s_pt = (float*)smu;   // alias aHi/aLo after phase 1
    __shared__ int s_opt[TB];
    __shared__ int s_pos[TB];
    __shared__ int s_cnt[N_OPT];
    __shared__ int s_base[N_OPT];

    const int tid  = threadIdx.x;
    const int r0   = blockIdx.x * TB;
    const int w    = tid >> 5, lane = tid & 31;
    const int g    = lane >> 2, t = lane & 3;
    const int m0   = w * 16;
    if (tid < N_OPT) s_cnt[tid] = 0;
    if (tid < TB) s_opt[tid] = opt[r0 + tid];
    __syncthreads();

    // ---------- fused scatter positions (PADDED bases) ----------
    int loc = 0;
    if (tid < TB) loc = atomicAdd(&s_cnt[s_opt[tid]], 1);
    __syncthreads();
    if (tid < N_OPT) {
        int base = 0;
#pragma unroll
        for (int q = 0; q < N_OPT; q++)
            base += (q < tid) ? ((g_counts[q] + 127) & ~127) : 0;
        s_base[tid] = base + atomicAdd(&g_cursor[tid], s_cnt[tid]);
        g_base[tid] = base;
        g_kcnt[tid] = g_counts[tid];
    }
    __syncthreads();
    if (tid < TB) {
        int p = s_base[s_opt[tid]] + loc;
        s_pos[tid] = p;
        g_perm[p] = r0 + tid;
    }

    // ---------- phase 1 (pipelined): h = relu(obs @ fW1^T + fb1) ----------
    float acc[8][4];
#pragma unroll
    for (int i = 0; i < 8; i++)
#pragma unroll
        for (int j = 0; j < 4; j++) acc[i][j] = 0.f;

#pragma unroll
    for (int it = 0; it < 2; it++) {
        int q = tid + it * 256;
        int row = q >> 3, p4 = (q & 7) << 2;
        cp16((u32)__cvta_generic_to_shared(w0H + row * 36 + p4), d_fW1h + row * 128 + p4);
        cp16((u32)__cvta_generic_to_shared(w0L + row * 36 + p4), d_fW1l + row * 128 + p4);
    }
    cp_commit();
    // obs chunk0 split (float4)
#pragma unroll
    for (int it = 0; it < 8; it++) {
        int e = tid + it * 256;              // 2048 float4 slots: 128 rows x 16
        int row = e >> 4, j = e & 15;
        float4 v = *(const float4*)(obs + (r0 + row) * OBS_DIM + 4 * j);
        u32 h0, l0, h1, l1;
        splitT(v.x, v.y, h0, l0);
        splitT(v.z, v.w, h1, l1);
        *(uint2*)(aHi + row * 36 + 2 * j) = make_uint2(h0, h1);
        *(uint2*)(aLo + row * 36 + 2 * j) = make_uint2(l0, l1);
    }

    float4 ov[8];
#pragma unroll
    for (int kc = 0; kc < 4; kc++) {
        u32* cAhi = (kc & 1) ? hHi : aHi;
        u32* cAlo = (kc & 1) ? hLo : aLo;
        u32* cWH  = (kc & 1) ? w1H : w0H;
        u32* cWL  = (kc & 1) ? w1L : w0L;
        cp_wait_all();
        __syncthreads();
        if (kc < 3) {
            u32* nWH = (kc & 1) ? w0H : w1H;
            u32* nWL = (kc & 1) ? w0L : w1L;
#pragma unroll
            for (int it = 0; it < 2; it++) {
                int q = tid + it * 256;
                int row = q >> 3, p4 = (q & 7) << 2;
                cp16((u32)__cvta_generic_to_shared(nWH + row * 36 + p4),
                     d_fW1h + row * 128 + (kc + 1) * 32 + p4);
                cp16((u32)__cvta_generic_to_shared(nWL + row * 36 + p4),
                     d_fW1l + row * 128 + (kc + 1) * 32 + p4);
            }
            cp_commit();
#pragma unroll
            for (int it = 0; it < 8; it++) {
                int e = tid + it * 256;
                int row = e >> 4, j = e & 15;
                ov[it] = *(const float4*)(obs + (r0 + row) * OBS_DIM + (kc + 1) * 64 + 4 * j);
            }
        }
        warp_mma64<4>(cAhi, cAlo, 36, cWH, cWL, 36, m0, lane, acc);
        if (kc < 3) {
            u32* nAhi = (kc & 1) ? aHi : hHi;
            u32* nAlo = (kc & 1) ? aLo : hLo;
#pragma unroll
            for (int it = 0; it < 8; it++) {
                int e = tid + it * 256;
                int row = e >> 4, j = e & 15;
                u32 h0, l0, h1, l1;
                splitT(ov[it].x, ov[it].y, h0, l0);
                splitT(ov[it].z, ov[it].w, h1, l1);
                *(uint2*)(nAhi + row * 36 + 2 * j) = make_uint2(h0, h1);
                *(uint2*)(nAlo + row * 36 + 2 * j) = make_uint2(l0, l1);
            }
        }
    }
    __syncthreads();

    const int r1 = m0 + g, r2 = m0 + g + 8;

    // epilogue -> h bf16 hi/lo
#pragma unroll
    for (int nt = 0; nt < 8; nt++) {
        int c = nt * 8 + 2 * t;
        float b0 = fb1[c], b1 = fb1[c + 1];
        float v0 = fmaxf(acc[nt][0] + b0, 0.f), v1 = fmaxf(acc[nt][1] + b1, 0.f);
        splitT(v0, v1, hHi[r1 * 36 + (c >> 1)], hLo[r1 * 36 + (c >> 1)]);
        float v2 = fmaxf(acc[nt][2] + b0, 0.f), v3 = fmaxf(acc[nt][3] + b1, 0.f);
        splitT(v2, v3, hHi[r2 * 36 + (c >> 1)], hLo[r2 * 36 + (c >> 1)]);
    }

    // ---------- phase 2: both fW2 halves + pW/tW in one round ----------
#pragma unroll
    for (int it = 0; it < 2; it++) {
        int q = tid + it * 256;
        int row = q >> 3, p4 = (q & 7) << 2;
        cp16((u32)__cvta_generic_to_shared(w0H + row * 36 + p4), d_fW2h + row * 32 + p4);
        cp16((u32)__cvta_generic_to_shared(w0L + row * 36 + p4), d_fW2l + row * 32 + p4);
        cp16((u32)__cvta_generic_to_shared(w1H + row * 36 + p4), d_fW2h + (64 + row) * 32 + p4);
        cp16((u32)__cvta_generic_to_shared(w1L + row * 36 + p4), d_fW2l + (64 + row) * 32 + p4);
    }
#pragma unroll
    for (int it = 0; it < 2; it++) {
        int q = tid + it * 256;
        const float* src = (q < 256) ? (pW + q * 4) : (tW + (q - 256) * 4);
        cp16((u32)__cvta_generic_to_shared(s_pt + q * 4), src);
    }
    cp_commit();
    cp_wait_all();
    __syncthreads();

    const int o1 = s_opt[r1], o2 = s_opt[r2];
    const int p1 = s_pos[r1], p2 = s_pos[r2];
    const int b1i = (p1 >> 7) * 8704 + (p1 & 127) * 68;   // tile-image base
    const int b2i = (p2 >> 7) * 8704 + (p2 & 127) * 68;
    float pv1 = 0.f, tv1 = 0.f, pv2 = 0.f, tv2 = 0.f;

#pragma unroll
    for (int nh = 0; nh < 2; nh++) {
        u32* wH = nh ? w1H : w0H;
        u32* wL = nh ? w1L : w0L;
        float acc2[8][4];
#pragma unroll
        for (int i = 0; i < 8; i++)
#pragma unroll
            for (int j = 0; j < 4; j++) acc2[i][j] = 0.f;
        warp_mma64<4>(hHi, hLo, 36, wH, wL, 36, m0, lane, acc2);

#pragma unroll
        for (int nt = 0; nt < 8; nt++) {
            int c = nh * 64 + nt * 8 + 2 * t;
            int cw = c >> 1;
            float b0 = fb2[c], b1 = fb2[c + 1];
            float v0 = fmaxf(acc2[nt][0] + b0, 0.f);
            float v1 = fmaxf(acc2[nt][1] + b1, 0.f);
            float v2 = fmaxf(acc2[nt][2] + b0, 0.f);
            float v3 = fmaxf(acc2[nt][3] + b1, 0.f);
            u32 hi, lo;
            splitT(v0, v1, hi, lo);
            g_sth[b1i + cw] = hi;
            g_stl[b1i + cw] = lo;
            splitT(v2, v3, hi, lo);
            g_sth[b2i + cw] = hi;
            g_stl[b2i + cw] = lo;
            pv1 += v0 * s_pt[o1 * 128 + c] + v1 * s_pt[o1 * 128 + c + 1];
            tv1 += v0 * s_pt[1024 + o1 * 128 + c] + v1 * s_pt[1024 + o1 * 128 + c + 1];
            pv2 += v2 * s_pt[o2 * 128 + c] + v3 * s_pt[o2 * 128 + c + 1];
            tv2 += v2 * s_pt[1024 + o2 * 128 + c] + v3 * s_pt[1024 + o2 * 128 + c + 1];
        }
    }

#pragma unroll
    for (int o = 1; o <= 2; o <<= 1) {
        pv1 += __shfl_xor_sync(0xffffffffu, pv1, o);
        tv1 += __shfl_xor_sync(0xffffffffu, tv1, o);
        pv2 += __shfl_xor_sync(0xffffffffu, pv2, o);
        tv2 += __shfl_xor_sync(0xffffffffu, tv2, o);
    }
    if (t == 0) {
        out_opt[r0 + r1]  = pv1 + pb[o1];
        out_term[r0 + r1] = 1.f / (1.f + expf(-(tv1 + tb[o1])));
        out_opt[r0 + r2]  = pv2 + pb[o2];
        out_term[r0 + r2] = 1.f / (1.f + expf(-(tv2 + tb[o2])));
    }
}

// =====================================================================
// Kernel 2: expert — ONE option per block; SMEM filled by 6 bulk copies
// =====================================================================
__global__ void __launch_bounds__(256, 2) expert_kernel(
    const float* __restrict__ ob1, const float* __restrict__ ob2,
    const int* __restrict__ act, float* __restrict__ out_logp)
{
    extern __shared__ u32 smu[];
    u32* stHi = smu;            // 128*68
    u32* stLo = smu + 8704;
    u32* wHi  = smu + 17408;    // 64*68
    u32* wLo  = smu + 21760;
    u32* w2h  = smu + 26112;    // 24*36
    u32* w2l  = smu + 26976;
    __shared__ int s_idx[TB];
    __shared__ int s_act[TB];
    __shared__ int s_gb[N_OPT];
    __shared__ int s_gc[N_OPT];
    __shared__ alignas(8) unsigned long long s_mbar;

    const int tid  = threadIdx.x;
    const int r0   = blockIdx.x * TB;
    const int w    = tid >> 5, lane = tid & 31;
    const int g    = lane >> 2, t = lane & 3;
    const int m0   = w * 16;
    const u32 mb   = (u32)__cvta_generic_to_shared(&s_mbar);

    if (tid == 0) mbar_init(mb, 1);
    if (tid < N_OPT) { s_gb[tid] = g_base[tid]; s_gc[tid] = g_kcnt[tid]; }
    if (blockIdx.x == 0 && tid < N_OPT) { g_counts[tid] = 0; g_cursor[tid] = 0; }
    __syncthreads();

    if (tid == 0) {
        mbar_expect(mb, 111360u);
        bulkcp((u32)__cvta_generic_to_shared(stHi), g_sth + (size_t)blockIdx.x * 8704, 34816u, mb);
        bulkcp((u32)__cvta_generic_to_shared(stLo), g_stl + (size_t)blockIdx.x * 8704, 34816u, mb);
    }

    // single option for the whole block (bases are 128-aligned)
    int o = 0;
#pragma unroll
    for (int q = 1; q < N_OPT; q++) o += (r0 >= s_gb[q]) ? 1 : 0;
    const int gb = s_gb[o], gc = s_gc[o];

    if (tid == 0) {
        bulkcp((u32)__cvta_generic_to_shared(wHi), d_oW1h + o * 4352, 17408u, mb);
        bulkcp((u32)__cvta_generic_to_shared(wLo), d_oW1l + o * 4352, 17408u, mb);
        bulkcp((u32)__cvta_generic_to_shared(w2h), d_oW2h + o * 864, 3456u, mb);
        bulkcp((u32)__cvta_generic_to_shared(w2l), d_oW2l + o * 864, 3456u, mb);
    }
    if (tid < TB) {
        int gi = g_perm[r0 + tid];           // stale at holes — outputs masked
        s_idx[tid] = gi;
        s_act[tid] = act[gi & (B_TOT - 1)];
    }
    __syncthreads();
    mbar_wait(mb, 0);

    // ---- MMA1 ----
    float acc[8][4];
#pragma unroll
    for (int i = 0; i < 8; i++)
#pragma unroll
        for (int q = 0; q < 4; q++) acc[i][q] = 0.f;
    warp_mma64<8>(stHi, stLo, 68, wHi, wLo, 68, m0, lane, acc);

    // ---- register epilogue -> A-fragments ----
    u32 ah1[8], al1[8], ah2[8], al2[8];
#pragma unroll
    for (int nt = 0; nt < 8; nt++) {
        int c = nt * 8 + 2 * t;
        float b0 = ob1[o * HID + c], b1 = ob1[o * HID + c + 1];
        splitT(fmaxf(acc[nt][0] + b0, 0.f), fmaxf(acc[nt][1] + b1, 0.f), ah1[nt], al1[nt]);
        splitT(fmaxf(acc[nt][2] + b0, 0.f), fmaxf(acc[nt][3] + b1, 0.f), ah2[nt], al2[nt]);
    }

    // ---- MMA2: logits ----
    float accL[3][4];
#pragma unroll
    for (int i = 0; i < 3; i++)
#pragma unroll
        for (int q = 0; q < 4; q++) accL[i][q] = 0.f;
    {
        const int mat = lane >> 3, rin = lane & 7;
        u32 b4h = (u32)__cvta_generic_to_shared(w2h) +
                  (u32)(((((mat >> 1) << 3) + rin) * 36 + ((mat & 1) << 2)) << 2);
        u32 b4l = (u32)__cvta_generic_to_shared(w2l) +
                  (u32)(((((mat >> 1) << 3) + rin) * 36 + ((mat & 1) << 2)) << 2);
        const int l16 = lane & 15;
        u32 b2off = (u32)(((16 + (l16 & 7)) * 36 + (((l16 >> 3) & 1) << 2)) << 2);
        u32 b2h = (u32)__cvta_generic_to_shared(w2h) + b2off;
        u32 b2l = (u32)__cvta_generic_to_shared(w2l) + b2off;
#pragma unroll
        for (int ks = 0; ks < 4; ks++) {
            u32 kb = ks * 32;
            u32 ah[4] = { ah1[2 * ks], ah2[2 * ks], ah1[2 * ks + 1], ah2[2 * ks + 1] };
            u32 al[4] = { al1[2 * ks], al2[2 * ks], al1[2 * ks + 1], al2[2 * ks + 1] };
            u32 bh[4], bl[4], bh2[2], bl2[2];
            ldsm4(bh, b4h + kb);
            ldsm4(bl, b4l + kb);
            ldsm2(bh2, b2h + kb);
            ldsm2(bl2, b2l + kb);
            mma16816(accL[0], ah, bh + 0);
            mma16816(accL[1], ah, bh + 2);
            mma16816(accL[2], ah, bh2);
            mma16816(accL[0], al, bh + 0);
            mma16816(accL[1], al, bh + 2);
            mma16816(accL[2], al, bh2);
            mma16816(accL[0], ah, bl + 0);
            mma16816(accL[1], ah, bl + 2);
            mma16816(accL[2], ah, bl2);
        }
    }

    // ---- softmax on fragments; skip hole rows ----
#pragma unroll
    for (int half = 0; half < 2; half++) {
        int rr = m0 + g + half * 8;
        float v[3][2];
#pragma unroll
        for (int nt = 0; nt < 3; nt++)
#pragma unroll
            for (int i = 0; i < 2; i++) {
                int c = nt * 8 + 2 * t + i;
                v[nt][i] = (c < ACT_N) ? accL[nt][half * 2 + i] + ob2[o * ACT_N + c]
                                       : -INFINITY;
            }
        float m = v[0][0];
#pragma unroll
        for (int nt = 0; nt < 3; nt++)
#pragma unroll
            for (int i = 0; i < 2; i++) m = fmaxf(m, v[nt][i]);
        m = fmaxf(m, __shfl_xor_sync(0xffffffffu, m, 1));
        m = fmaxf(m, __shfl_xor_sync(0xffffffffu, m, 2));
        float S = 0.f;
#pragma unroll
        for (int nt = 0; nt < 3; nt++)
#pragma unroll
            for (int i = 0; i < 2; i++) S += expf(v[nt][i] - m);
        S += __shfl_xor_sync(0xffffffffu, S, 1);
        S += __shfl_xor_sync(0xffffffffu, S, 2);
        int a = s_act[rr];
        float cand = 0.f;
#pragma unroll
        for (int nt = 0; nt < 3; nt++)
#pragma unroll
            for (int i = 0; i < 2; i++) {
                int c = nt * 8 + 2 * t + i;
                cand = (c == a) ? v[nt][i] : cand;
            }
        cand += __shfl_xor_sync(0xffffffffu, cand, 1);
        cand += __shfl_xor_sync(0xffffffffu, cand, 2);
        bool real = (r0 + rr - gb) < gc;
        if (t == 0 && real)
            out_logp[s_idx[rr]] = cand - m - logf(S);
    }
}

// =====================================================================
extern "C" void kernel_launch(void* const* d_in, const int* in_sizes, int n_in,
                              void* d_out, int out_size)
{
    const float* obs = (const float*)d_in[0];
    const int*   act = (const int*)  d_in[1];
    const int*   opt = (const int*)  d_in[2];
    const float* fW1 = (const float*)d_in[3];
    const float* fb1 = (const float*)d_in[4];
    const float* fW2 = (const float*)d_in[5];
    const float* fb2 = (const float*)d_in[6];
    const float* pW  = (const float*)d_in[7];
    const float* pb  = (const float*)d_in[8];
    const float* tW  = (const float*)d_in[9];
    const float* tb  = (const float*)d_in[10];
    const float* oW1 = (const float*)d_in[11];
    const float* ob1 = (const float*)d_in[12];
    const float* oW2 = (const float*)d_in[13];
    const float* ob2 = (const float*)d_in[14];

    float* out_logp = (float*)d_out;
    float* out_opt  = out_logp + B_TOT;
    float* out_term = out_logp + 2 * B_TOT;

    const int smem1 = 27648 * 4;   // 110,592 B
    const int smem4 = 27840 * 4;   // 111,360 B
    cudaFuncSetAttribute(trunk_kernel,  cudaFuncAttributeMaxDynamicSharedMemorySize, smem1);
    cudaFuncSetAttribute(expert_kernel, cudaFuncAttributeMaxDynamicSharedMemorySize, smem4);

    split_kernel<<<200, 256>>>(fW1, fW2, oW1, oW2, opt);
    trunk_kernel<<<B_TOT / TB, 256, smem1>>>(obs, opt, fb1, fb2,
                                             pW, pb, tW, tb, out_opt, out_term);
    expert_kernel<<<EGRID, 256, smem4>>>(ob1, ob2, act, out_logp);
}